// round 5
// baseline (speedup 1.0000x reference)
#include <cuda_runtime.h>
#include <math.h>

#define T_LEN 131072
#define NL 27
#define SD 512
#define QD 256
#define KC (NL*32)   // 864

typedef unsigned long long u64;

// ---------------- device scratch (no allocations allowed) ----------------
__device__ float g_x0[32*(size_t)T_LEN];       // residual ping
__device__ float g_x1[32*(size_t)T_LEN];       // residual pong
__device__ float g_G [(size_t)KC*T_LEN];       // all gate outputs [864][T]
__device__ float g_h [(size_t)SD*T_LEN];       // relu(Wall@G + c0)
__device__ float g_Wall[SD*KC];                // folded Wp1 @ Wskip_i
__device__ float g_c0[SD];
__device__ float g_bsum[SD];

// ---------------- f32x2 helpers ----------------
__device__ __forceinline__ u64 pk2(float x){ u64 r; asm("mov.b64 %0,{%1,%1};":"=l"(r):"f"(x)); return r; }
__device__ __forceinline__ void fma2(u64 &d, u64 a, u64 b){ asm("fma.rn.f32x2 %0,%1,%2,%0;":"+l"(d):"l"(a),"l"(b)); }
__device__ __forceinline__ u64 add2(u64 a, u64 b){ u64 r; asm("add.rn.f32x2 %0,%1,%2;":"=l"(r):"l"(a),"l"(b)); return r; }
__device__ __forceinline__ void unpk(u64 v, float &a, float &b){ asm("mov.b64 {%0,%1},%2;":"=f"(a),"=f"(b):"l"(v)); }

// ---------------- initial conv: [1,T] -> [32,T], k=3, pad=1 ----------------
__global__ void k_conv0(const float* __restrict__ x, const float* __restrict__ Wc,
                        const float* __restrict__ bc){
    __shared__ float4 w[32];
    int tid = threadIdx.x;
    if (tid < 32) w[tid] = make_float4(Wc[tid*3], Wc[tid*3+1], Wc[tid*3+2], bc[tid]);
    __syncthreads();
    int t = blockIdx.x*256 + tid;
    float xm = (t > 0)        ? x[t-1] : 0.f;
    float x0 = x[t];
    float xp = (t < T_LEN-1)  ? x[t+1] : 0.f;
#pragma unroll
    for (int o = 0; o < 32; o++){
        float4 q = w[o];
        g_x0[(size_t)o*T_LEN + t] = q.w + q.x*xm + q.y*x0 + q.z*xp;
    }
}

// ---------------- bsum[m] = sum_i bskip[i][m] ----------------
__global__ void k_bsum(const float* __restrict__ bskip){
    int m = blockIdx.x*256 + threadIdx.x;
    if (m < SD){
        float s = 0.f;
        for (int i = 0; i < NL; i++) s += bskip[i*SD + m];
        g_bsum[m] = s;
    }
}

// ---------------- c0[s] = bp1[s] + sum_m Wp1[s][m]*bsum[m] ----------------
__global__ void k_c0(const float* __restrict__ Wp1, const float* __restrict__ bp1){
    __shared__ float red[128];
    int s = blockIdx.x, tid = threadIdx.x;
    float acc = 0.f;
    for (int m = tid; m < SD; m += 128) acc += Wp1[s*SD + m]*g_bsum[m];
    red[tid] = acc; __syncthreads();
    for (int st = 64; st > 0; st >>= 1){
        if (tid < st) red[tid] += red[tid+st];
        __syncthreads();
    }
    if (tid == 0) g_c0[s] = red[0] + bp1[s];
}

// ---------------- Wall[s][i*32+c] = sum_m Wp1[s][m]*Wskip[i][m][c] ----------------
__global__ void k_fold(const float* __restrict__ Wp1, const float* __restrict__ Wsk){
    __shared__ float wr[16*512];               // 16 rows of Wp1
    int s0 = blockIdx.x*16, tid = threadIdx.x; // 864 threads: tid = i*32+c
    for (int i = tid; i < 16*512; i += 864)
        wr[i] = Wp1[(size_t)(s0 + (i>>9))*SD + (i & 511)];
    __syncthreads();
    int i = tid >> 5, c = tid & 31;
    float acc[16];
#pragma unroll
    for (int u = 0; u < 16; u++) acc[u] = 0.f;
    const float* wp = Wsk + (size_t)i*SD*32 + c;
    for (int m = 0; m < SD; m++){
        float v = wp[m*32];
#pragma unroll
        for (int u = 0; u < 16; u++) acc[u] += wr[u*512 + m]*v;
    }
#pragma unroll
    for (int u = 0; u < 16; u++) g_Wall[(s0+u)*KC + tid] = acc[u];
}

// ---------------- one WaveNet layer ----------------
// smem floats: sWt 3072 | sWs 3072 | sWd 1024 | biases 96 | sxm/sx0/sxp 4096*3 | sg 4096
#define LSMEM_F (7264 + 16384)
__global__ void __launch_bounds__(256) k_layer(
    const float* __restrict__ Wt, const float* __restrict__ bt,
    const float* __restrict__ Ws, const float* __restrict__ bs,
    const float* __restrict__ Wd, const float* __restrict__ bd,
    int layer, int dil)
{
    extern __shared__ float sm[];
    float* sWt = sm;              // [c*3+k][o]  (o fastest -> conflict-free reads)
    float* sWs = sm + 3072;
    float* sWd = sm + 6144;       // [c][o]
    float* sbt = sm + 7168; float* sbs = sm + 7200; float* sbd = sm + 7232;
    float* sxm = sm + 7264;       // [c][128]
    float* sx0 = sm + 7264 + 4096;
    float* sxp = sm + 7264 + 8192;
    float* sg  = sm + 7264 + 12288;

    const float* xin  = (layer & 1) ? g_x1 : g_x0;
    float*       xout = (layer & 1) ? g_x0 : g_x1;

    int tid = threadIdx.x;
    int tb  = blockIdx.x*128;

    const float* Wtl = Wt + layer*3072;
    const float* Wsl = Ws + layer*3072;
    const float* Wdl = Wd + layer*1024;
    for (int i = tid; i < 3072; i += 256){
        int o = i/96, ck = i%96;
        sWt[ck*32 + o] = Wtl[i];
        sWs[ck*32 + o] = Wsl[i];
    }
    for (int i = tid; i < 1024; i += 256){
        int o = i >> 5, c = i & 31;
        sWd[c*32 + o] = Wdl[i];
    }
    if (tid < 32){ sbt[tid] = bt[layer*32+tid]; sbs[tid] = bs[layer*32+tid]; sbd[tid] = bd[layer*32+tid]; }
    for (int i = tid; i < 4096; i += 256){
        int c = i >> 7, tt = i & 127; int t = tb + tt;
        sx0[i] = xin[(size_t)c*T_LEN + t];
        int tm = t - dil; sxm[i] = (tm >= 0)    ? xin[(size_t)c*T_LEN + tm] : 0.f;
        int tp = t + dil; sxp[i] = (tp < T_LEN) ? xin[(size_t)c*T_LEN + tp] : 0.f;
    }
    __syncthreads();

    int o = tid >> 3, tq = tid & 7, t0 = tq*16;   // 1 output ch x 16 timesteps
    u64 a[8], b[8];
    {
        u64 ia = pk2(sbt[o]), ib = pk2(sbs[o]);
#pragma unroll
        for (int j = 0; j < 8; j++){ a[j] = ia; b[j] = ib; }
    }
#pragma unroll 2
    for (int c = 0; c < 32; c++){
        u64 wa0 = pk2(sWt[(c*3+0)*32+o]), wa1 = pk2(sWt[(c*3+1)*32+o]), wa2 = pk2(sWt[(c*3+2)*32+o]);
        u64 wb0 = pk2(sWs[(c*3+0)*32+o]), wb1 = pk2(sWs[(c*3+1)*32+o]), wb2 = pk2(sWs[(c*3+2)*32+o]);
        const u64* pm = (const u64*)&sxm[c*128 + t0];
        const u64* p0 = (const u64*)&sx0[c*128 + t0];
        const u64* pp = (const u64*)&sxp[c*128 + t0];
#pragma unroll
        for (int j = 0; j < 8; j++){
            fma2(a[j], wa0, pm[j]); fma2(a[j], wa1, p0[j]); fma2(a[j], wa2, pp[j]);
            fma2(b[j], wb0, pm[j]); fma2(b[j], wb1, p0[j]); fma2(b[j], wb2, pp[j]);
        }
    }
    // g = tanh(a)*sigmoid(b)
    float* dstS = &sg[o*128 + t0];
    float* dstG = &g_G[((size_t)layer*32 + o)*T_LEN + tb + t0];
#pragma unroll
    for (int j = 0; j < 8; j++){
        float av0, av1, bv0, bv1;
        unpk(a[j], av0, av1); unpk(b[j], bv0, bv1);
        float e0 = __expf(2.f*fminf(fmaxf(av0, -15.f), 15.f));
        float e1 = __expf(2.f*fminf(fmaxf(av1, -15.f), 15.f));
        float th0 = __fdividef(e0 - 1.f, e0 + 1.f);
        float th1 = __fdividef(e1 - 1.f, e1 + 1.f);
        float sg0 = __fdividef(1.f, 1.f + __expf(-bv0));
        float sg1 = __fdividef(1.f, 1.f + __expf(-bv1));
        float gv0 = th0*sg0, gv1 = th1*sg1;
        dstS[2*j] = gv0; dstS[2*j+1] = gv1;
        float2 gw; gw.x = gv0; gw.y = gv1;
        *(float2*)&dstG[2*j] = gw;
    }
    __syncthreads();

    // dense 1x1 + residual
    u64 r[8];
    {
        u64 ir = pk2(sbd[o]);
#pragma unroll
        for (int j = 0; j < 8; j++) r[j] = ir;
    }
#pragma unroll 4
    for (int c = 0; c < 32; c++){
        u64 w = pk2(sWd[c*32 + o]);
        const u64* pg = (const u64*)&sg[c*128 + t0];
#pragma unroll
        for (int j = 0; j < 8; j++) fma2(r[j], w, pg[j]);
    }
    const u64* px = (const u64*)&sx0[o*128 + t0];
    u64* dx = (u64*)&xout[(size_t)o*T_LEN + tb + t0];
#pragma unroll
    for (int j = 0; j < 8; j++) dx[j] = add2(r[j], px[j]);
}

// ---------------- GEMM: C[M][T] = (relu?)(A[M][K] @ B[K][T] + bias) ----------------
// block tile 64 rows x 128 cols, thread = 4 rows x 8 cols (f32x2 pairs)
__device__ __forceinline__ void gemm_body(const float* __restrict__ A, const float* __restrict__ B,
                                          const float* __restrict__ bias, float* __restrict__ C,
                                          int K, bool relu)
{
    __shared__ float As[32][68];   // [k][row], pad 68 -> conflict-free + aligned LDS.128
    __shared__ float Bs[32][128];
    int tid = threadIdx.x;
    int tb = blockIdx.x*128, m0 = blockIdx.y*64;
    int tx = tid & 15, ty = tid >> 4;
    int c0 = tx*8, r0 = ty*4;
    u64 acc[4][4];
#pragma unroll
    for (int i = 0; i < 4; i++)
#pragma unroll
        for (int j = 0; j < 4; j++) acc[i][j] = 0ull;

    for (int kc = 0; kc < K; kc += 32){
#pragma unroll
        for (int u = 0; u < 2; u++){           // A tile 64x32, transpose on store
            int fi = tid + u*256; int row = fi >> 3, kq = fi & 7;
            float4 v = *(const float4*)&A[(size_t)(m0+row)*K + kc + kq*4];
            As[kq*4+0][row] = v.x; As[kq*4+1][row] = v.y;
            As[kq*4+2][row] = v.z; As[kq*4+3][row] = v.w;
        }
#pragma unroll
        for (int u = 0; u < 4; u++){           // B tile 32x128
            int fi = tid + u*256; int kr = fi >> 5, cq = fi & 31;
            *(float4*)&Bs[kr][cq*4] = *(const float4*)&B[(size_t)(kc+kr)*T_LEN + tb + cq*4];
        }
        __syncthreads();
#pragma unroll 8
        for (int k = 0; k < 32; k++){
            float4 av = *(const float4*)&As[k][r0];
            u64 a0 = pk2(av.x), a1 = pk2(av.y), a2 = pk2(av.z), a3 = pk2(av.w);
            const u64* bv = (const u64*)&Bs[k][c0];
#pragma unroll
            for (int j = 0; j < 4; j++){
                u64 bb = bv[j];
                fma2(acc[0][j], a0, bb); fma2(acc[1][j], a1, bb);
                fma2(acc[2][j], a2, bb); fma2(acc[3][j], a3, bb);
            }
        }
        __syncthreads();
    }
#pragma unroll
    for (int i = 0; i < 4; i++){
        int row = m0 + r0 + i;
        float bv = bias[row];
        float* cp = &C[(size_t)row*T_LEN + tb + c0];
#pragma unroll
        for (int j = 0; j < 4; j++){
            float v0, v1; unpk(acc[i][j], v0, v1);
            v0 += bv; v1 += bv;
            if (relu){ v0 = fmaxf(v0, 0.f); v1 = fmaxf(v1, 0.f); }
            cp[2*j] = v0; cp[2*j+1] = v1;
        }
    }
}

__global__ void __launch_bounds__(256) k_gemm2(){          // h = relu(Wall@G + c0)
    gemm_body(g_Wall, g_G, g_c0, g_h, KC, true);
}
__global__ void __launch_bounds__(256) k_gemm3(const float* __restrict__ Wp2,
                                               const float* __restrict__ bp2,
                                               float* __restrict__ out){
    gemm_body(Wp2, g_h, bp2, out, SD, false);
}

// ---------------- in-place log_softmax over 256 channels ----------------
__global__ void k_lsm(float* __restrict__ out){
    int t = blockIdx.x*256 + threadIdx.x;
    float m = -1e30f;
#pragma unroll 8
    for (int q = 0; q < QD; q++) m = fmaxf(m, out[(size_t)q*T_LEN + t]);
    float s = 0.f;
#pragma unroll 8
    for (int q = 0; q < QD; q++) s += __expf(out[(size_t)q*T_LEN + t] - m);
    float lz = m + logf(s);
#pragma unroll 8
    for (int q = 0; q < QD; q++) out[(size_t)q*T_LEN + t] -= lz;
}

// ---------------- launch ----------------
extern "C" void kernel_launch(void* const* d_in, const int* in_sizes, int n_in,
                              void* d_out, int out_size){
    const float* x     = (const float*)d_in[0];
    const float* Wc    = (const float*)d_in[1];
    const float* bc    = (const float*)d_in[2];
    const float* Wt    = (const float*)d_in[3];
    const float* bt    = (const float*)d_in[4];
    const float* Ws    = (const float*)d_in[5];
    const float* bs    = (const float*)d_in[6];
    const float* Wskip = (const float*)d_in[7];
    const float* bskip = (const float*)d_in[8];
    const float* Wd    = (const float*)d_in[9];
    const float* bd    = (const float*)d_in[10];
    const float* Wp1   = (const float*)d_in[11];
    const float* bp1   = (const float*)d_in[12];
    const float* Wp2   = (const float*)d_in[13];
    const float* bp2   = (const float*)d_in[14];
    float* out = (float*)d_out;

    static const int DIL[NL] = {1,2,4,8,16,32,64,128,256,
                                1,2,4,8,16,32,64,128,256,
                                1,2,4,8,16,32,64,128,256};

    cudaFuncSetAttribute(k_layer, cudaFuncAttributeMaxDynamicSharedMemorySize, LSMEM_F*4);

    k_bsum<<<2, 256>>>(bskip);
    k_c0<<<SD, 128>>>(Wp1, bp1);
    k_fold<<<32, 864>>>(Wp1, Wskip);
    k_conv0<<<T_LEN/256, 256>>>(x, Wc, bc);
    for (int i = 0; i < NL; i++)
        k_layer<<<T_LEN/128, 256, LSMEM_F*4>>>(Wt, bt, Ws, bs, Wd, bd, i, DIL[i]);
    k_gemm2<<<dim3(T_LEN/128, SD/64), 256>>>();
    k_gemm3<<<dim3(T_LEN/128, QD/64), 256>>>(Wp2, bp2, out);
    k_lsm<<<T_LEN/256, 256>>>(out);
}